// round 7
// baseline (speedup 1.0000x reference)
#include <cuda_runtime.h>

// 2x nearest-neighbor upsample:
// in:  float32 [16, 64, 256, 256]  (1024 planes of 256x256)
// out: float32 [16, 64, 512, 512]
//
// Thread indexing over OUTPUT quads (one float4 of output per thread per row):
//   idx -> (plane, h_in, ow4); input float2 index == idx (same linear index).
//   q = (x,x,y,y) stored to output rows 2h and 2h+1 at column ow4.
// Per warp: 1 x LDG.64 (256B contiguous) + 2 x STG.128 (512B contiguous).
// Both streams are touch-once -> streaming cache hints (__ldcs / __stcs)
// to keep L2 from caching dead data and maximize HBM streaming efficiency.

#define W_OUT4 128                  // float4 per output row (512/4)

__global__ void __launch_bounds__(256) upsample2x_outidx_kernel(
    const float2* __restrict__ in2, float4* __restrict__ out4, int total)
{
    int idx = blockIdx.x * blockDim.x + threadIdx.x;
    if (idx >= total) return;

    // idx -> (plane, h, ow4); input float2 index == idx
    int ow4   = idx & (W_OUT4 - 1);         // 0..127
    int h     = (idx >> 7) & 255;           // 0..255
    int plane = idx >> 15;                  // 0..1023

    float2 v = __ldcs(&in2[idx]);           // read-once: evict-first
    float4 q = make_float4(v.x, v.x, v.y, v.y);

    // output row 2h of this plane, column ow4 (float4 units)
    long long base = ((long long)plane * 512 + 2 * h) * W_OUT4 + ow4;

    __stcs(&out4[base],          q);        // row 2h   (streaming store)
    __stcs(&out4[base + W_OUT4], q);        // row 2h+1 (streaming store)
}

extern "C" void kernel_launch(void* const* d_in, const int* in_sizes, int n_in,
                              void* d_out, int out_size)
{
    const float2* in2 = (const float2*)d_in[0];
    float4* out4 = (float4*)d_out;

    int total = in_sizes[0] / 2;            // 33,554,432 threads
    int threads = 256;
    int blocks = (total + threads - 1) / threads;

    upsample2x_outidx_kernel<<<blocks, threads>>>(in2, out4, total);
}

// round 8
// speedup vs baseline: 1.0083x; 1.0083x over previous
#include <cuda_runtime.h>

// 2x nearest-neighbor upsample:
// in:  float32 [16, 64, 256, 256]  (1024 planes of 256x256)
// out: float32 [16, 64, 512, 512]
//
// Thread indexing over output quads with a 2-input-row vertical unroll:
//   idx -> (plane, hp, ow4); thread loads input rows 2hp and 2hp+1 (float2
//   each, independent -> MLP 2) and writes output rows 4hp..4hp+3 (one
//   float4 per row). Every store instruction is lane-contiguous:
//   per warp 2 x LDG.64 (256B) + 4 x STG.128 (512B each).
// Plain loads/stores: streaming cache hints measured neutral (R7).

#define W_IN2  128                  // float2 per input row (256/2)
#define W_OUT4 128                  // float4 per output row (512/4)

__global__ void __launch_bounds__(256) upsample2x_v2_kernel(
    const float2* __restrict__ in2, float4* __restrict__ out4, int total)
{
    int idx = blockIdx.x * blockDim.x + threadIdx.x;
    if (idx >= total) return;

    // idx -> (plane, hp, ow4)
    int ow4   = idx & (W_OUT4 - 1);         // 0..127
    int hp    = (idx >> 7) & 127;           // 0..127 (pair of input rows)
    int plane = idx >> 14;                  // 0..1023

    // input float2 indices for rows 2hp and 2hp+1, column ow4
    long long ibase = ((long long)plane * 256 + 2 * hp) * W_IN2 + ow4;
    float2 a = in2[ibase];                  // row 2hp
    float2 b = in2[ibase + W_IN2];          // row 2hp+1  (independent load)

    float4 qa = make_float4(a.x, a.x, a.y, a.y);
    float4 qb = make_float4(b.x, b.x, b.y, b.y);

    // output row 4hp of this plane, column ow4 (float4 units)
    long long obase = ((long long)plane * 512 + 4 * hp) * W_OUT4 + ow4;

    out4[obase]              = qa;          // row 4hp
    out4[obase + W_OUT4]     = qa;          // row 4hp+1
    out4[obase + 2 * W_OUT4] = qb;          // row 4hp+2
    out4[obase + 3 * W_OUT4] = qb;          // row 4hp+3
}

extern "C" void kernel_launch(void* const* d_in, const int* in_sizes, int n_in,
                              void* d_out, int out_size)
{
    const float2* in2 = (const float2*)d_in[0];
    float4* out4 = (float4*)d_out;

    int total = in_sizes[0] / 4;            // 16,777,216 threads (2 input rows each)
    int threads = 256;
    int blocks = (total + threads - 1) / threads;

    upsample2x_v2_kernel<<<blocks, threads>>>(in2, out4, total);
}

// round 9
// speedup vs baseline: 1.0172x; 1.0088x over previous
#include <cuda_runtime.h>

// 2x nearest-neighbor upsample:
// in:  float32 [16, 64, 256, 256]  (1024 planes of 256x256)
// out: float32 [16, 64, 512, 512]
//
// Converged structure (R4): thread indexing over OUTPUT quads.
//   idx -> (plane, h_in, ow4); input float2 index == idx (same linear index).
//   q = (x,x,y,y) stored to output rows 2h and 2h+1 at column ow4.
// Per warp: 1 x LDG.64 (256B contiguous) + 2 x STG.128 (512B contiguous).
// Measured pinned at HBM mixed-stream ceiling (~6.6 TB/s, DRAM ~84%):
//   - streaming cache hints: neutral (R7)
//   - 2-row vertical unroll (MLP 2): neutral (R8)
// This probe: 512-thread blocks (halves CTA count); predicted neutral.

#define W_OUT4 128                  // float4 per output row (512/4)

__global__ void __launch_bounds__(512) upsample2x_outidx_kernel(
    const float2* __restrict__ in2, float4* __restrict__ out4, int total)
{
    int idx = blockIdx.x * blockDim.x + threadIdx.x;
    if (idx >= total) return;

    // idx -> (plane, h, ow4); input float2 index == idx
    int ow4   = idx & (W_OUT4 - 1);         // 0..127
    int h     = (idx >> 7) & 255;           // 0..255
    int plane = idx >> 15;                  // 0..1023

    float2 v = in2[idx];
    float4 q = make_float4(v.x, v.x, v.y, v.y);

    // output row 2h of this plane, column ow4 (float4 units)
    long long base = ((long long)plane * 512 + 2 * h) * W_OUT4 + ow4;

    out4[base]          = q;   // row 2h
    out4[base + W_OUT4] = q;   // row 2h+1
}

extern "C" void kernel_launch(void* const* d_in, const int* in_sizes, int n_in,
                              void* d_out, int out_size)
{
    const float2* in2 = (const float2*)d_in[0];
    float4* out4 = (float4*)d_out;

    int total = in_sizes[0] / 2;            // 33,554,432 threads
    int threads = 512;
    int blocks = (total + threads - 1) / threads;

    upsample2x_outidx_kernel<<<blocks, threads>>>(in2, out4, total);
}